// round 3
// baseline (speedup 1.0000x reference)
#include <cuda_runtime.h>

// Geometric product in Cl(3,0,1): out[n,k] = sum_{i,j} a[n,i] b[n,j] C[i,j,k]
// Structure constants baked in at compile time (metric = 1,1,1,0).
//
// R3: stream b from smem quad-by-quad to cut live registers (56 -> ~42),
// allowing 6 CTAs/SM instead of 4. All global traffic stays unit-stride;
// smem stays XOR-swizzled conflict-free.

static __host__ __device__ constexpr int cayley_sign(int A, int B) {
    if (A & B & 8) return 0;            // degenerate generator e3 (metric 0)
    int s = 0;
    int sa = A >> 1;
    while (sa) {
        int x = sa & B;
        while (x) { s += 1; x &= (x - 1); }
        sa >>= 1;
    }
    return (s & 1) ? -1 : 1;
}

// Swizzled position for flat float4 index idx within a 1024-float4 tile:
//   r = idx>>2 (row), c = idx&3 (quad); pos = 4r | (c ^ ((r>>1)&3))
// Conflict-free for both unit-stride staging and per-row access.
static __device__ __forceinline__ int swz(int idx) {
    const int r = idx >> 2;
    const int c = idx & 3;
    return (r << 2) | (c ^ ((r >> 1) & 3));
}

__global__ void __launch_bounds__(256, 6)
gp_kernel(const float4* __restrict__ a4,
          const float4* __restrict__ b4,
          float4* __restrict__ o4,
          int n_rows) {
    __shared__ float4 sa[1024];   // 16 KB
    __shared__ float4 sb[1024];   // 16 KB

    const int t     = threadIdx.x;
    const int base4 = blockIdx.x * 1024;
    const int row0  = blockIdx.x * 256;

    // ---- Stage a and b: unit-stride global loads, swizzled smem writes ----
    if (row0 + 256 <= n_rows) {
        #pragma unroll
        for (int v = 0; v < 4; ++v) {
            const int idx = v * 256 + t;
            const int pos = swz(idx);
            sa[pos] = a4[base4 + idx];
            sb[pos] = b4[base4 + idx];
        }
    } else {
        #pragma unroll
        for (int v = 0; v < 4; ++v) {
            const int idx = v * 256 + t;
            const int pos = swz(idx);
            if ((base4 + idx) < n_rows * 4) {
                sa[pos] = a4[base4 + idx];
                sb[pos] = b4[base4 + idx];
            } else {
                sa[pos] = make_float4(0.f, 0.f, 0.f, 0.f);
                sb[pos] = make_float4(0.f, 0.f, 0.f, 0.f);
            }
        }
    }
    __syncthreads();

    const int s = (t >> 1) & 3;

    // ---- Read own a row fully (4 conflict-free LDS.128) ----
    float a[16];
    #pragma unroll
    for (int v = 0; v < 4; ++v) {
        const float4 va = sa[(t << 2) | (v ^ s)];
        a[v * 4 + 0] = va.x; a[v * 4 + 1] = va.y;
        a[v * 4 + 2] = va.z; a[v * 4 + 3] = va.w;
    }

    float c[16];
    #pragma unroll
    for (int k = 0; k < 16; ++k) c[k] = 0.0f;

    // ---- Stream b one quad at a time: 4 live b floats, 48 FMAs per quad ----
    #pragma unroll
    for (int v = 0; v < 4; ++v) {
        const float4 vb = sb[(t << 2) | (v ^ s)];
        const float bb0 = vb.x, bb1 = vb.y, bb2 = vb.z, bb3 = vb.w;

        #pragma unroll
        for (int A = 0; A < 16; ++A) {
            #pragma unroll
            for (int j = 0; j < 4; ++j) {
                const int B = v * 4 + j;
                const int sg = cayley_sign(A, B);
                const float bv = (j == 0) ? bb0 : (j == 1) ? bb1
                               : (j == 2) ? bb2 : bb3;
                if (sg == 1) {
                    c[A ^ B] = fmaf(a[A], bv, c[A ^ B]);
                } else if (sg == -1) {
                    c[A ^ B] = fmaf(-a[A], bv, c[A ^ B]);
                }
            }
        }
        // Fence: keeps ptxas from hoisting the next quad's LDS (which would
        // re-inflate live registers back to the full b[16]).
        __syncwarp();
    }

    // ---- Write own output row into sa (own region; no pre-sync needed) ----
    #pragma unroll
    for (int v = 0; v < 4; ++v) {
        sa[(t << 2) | (v ^ s)] = make_float4(c[v * 4 + 0], c[v * 4 + 1],
                                             c[v * 4 + 2], c[v * 4 + 3]);
    }
    __syncthreads();

    // ---- Gather + unit-stride global stores ----
    if (row0 + 256 <= n_rows) {
        #pragma unroll
        for (int v = 0; v < 4; ++v) {
            const int idx = v * 256 + t;
            o4[base4 + idx] = sa[swz(idx)];
        }
    } else {
        #pragma unroll
        for (int v = 0; v < 4; ++v) {
            const int idx = v * 256 + t;
            if ((base4 + idx) < n_rows * 4)
                o4[base4 + idx] = sa[swz(idx)];
        }
    }
}

extern "C" void kernel_launch(void* const* d_in, const int* in_sizes, int n_in,
                              void* d_out, int out_size) {
    const float4* a4 = (const float4*)d_in[0];
    const float4* b4 = (const float4*)d_in[1];
    // d_in[2] is the Cayley tensor; values are baked in at compile time.
    float4* o4 = (float4*)d_out;

    const int n_rows = in_sizes[0] / 16;
    const int blocks = (n_rows + 255) / 256;
    gp_kernel<<<blocks, 256>>>(a4, b4, o4, n_rows);
}